// round 1
// baseline (speedup 1.0000x reference)
#include <cuda_runtime.h>
#include <math.h>

#define S  2048
#define D  1024
#define H  16
#define HD 64
#define L  2
#define MH 1024
#define FF (2 * D)

// ---------------- scratch (device globals; no allocation allowed) ----------
__device__ float g_x[S * D];     // activations
__device__ float g_xr[S * D];    // rope(x)
__device__ float g_q[S * D];     // q / attn_out / ff_out / head h1
__device__ float g_k[S * D];     // k / head h2
__device__ float g_v[S * D];     // v
__device__ float g_ctx[S * D];   // attention context
__device__ float g_ff[S * FF];   // ffn hidden

// ---------------- gather: x[s,:] = node_emb[tile_ids[s],:] -----------------
__global__ void gather_kernel(const float* __restrict__ emb,
                              const int* __restrict__ ids,
                              float* __restrict__ x) {
    int s = blockIdx.x;
    int id = ids[s];
    const float4* src = (const float4*)(emb + (size_t)id * D);
    float4* dst = (float4*)(x + (size_t)s * D);
    dst[threadIdx.x] = src[threadIdx.x];
}

// ---------------- 2D RoPE ---------------------------------------------------
// first 512 dims rotated by row pos, last 512 by col pos; hh=256 pairs each.
__global__ void rope_kernel(const float* __restrict__ x,
                            const int* __restrict__ ids,
                            const int* __restrict__ nyp,
                            float* __restrict__ xr) {
    int s = blockIdx.x;
    int j = threadIdx.x;  // 0..255
    int id = ids[s];
    int Ny = nyp[0];
    float rowp = (float)(id / Ny);
    float colp = (float)(id % Ny);
    float theta = powf(10000.f, -((float)j) * (1.f / 256.f));
    float a1 = rowp * theta;
    float a2 = colp * theta;
    float s1, c1, s2, c2;
    sincosf(a1, &s1, &c1);
    sincosf(a2, &s2, &c2);
    const float* xs = x + (size_t)s * D;
    float* xd = xr + (size_t)s * D;
    float x1 = xs[j], x2 = xs[j + 256];
    xd[j]       = x1 * c1 - x2 * s1;
    xd[j + 256] = x1 * s1 + x2 * c1;
    float y1 = xs[j + 512], y2 = xs[j + 768];
    xd[j + 512] = y1 * c2 - y2 * s2;
    xd[j + 768] = y1 * s2 + y2 * c2;
}

// ---------------- GEMM: C[M,N] = A[M,K] @ W[K,N] + bias (opt relu) ----------
// 128x128 block, BK=8, 256 threads, 8x8 micro-tile per thread.
__global__ __launch_bounds__(256) void gemm_kernel(
    const float* __restrict__ A, const float* __restrict__ W,
    const float* __restrict__ bias, float* __restrict__ C,
    int M, int N, int K, int relu) {
    __shared__ float As[8][128];  // transposed: As[k][m]
    __shared__ float Bs[8][128];
    int tid = threadIdx.x;
    int tx = tid & 15;
    int ty = tid >> 4;
    int bm = blockIdx.y * 128;
    int bn = blockIdx.x * 128;

    float acc[8][8];
#pragma unroll
    for (int i = 0; i < 8; i++)
#pragma unroll
        for (int j = 0; j < 8; j++) acc[i][j] = 0.f;

    int arow = tid >> 1;         // 0..127
    int acol = (tid & 1) * 4;    // 0 or 4
    int brow = tid >> 5;         // 0..7
    int bcol = (tid & 31) * 4;   // 0..124
    const float* Aptr = A + (size_t)(bm + arow) * K + acol;
    const float* Wptr = W + (size_t)brow * N + bn + bcol;

    for (int k0 = 0; k0 < K; k0 += 8) {
        float4 av = *(const float4*)(Aptr + k0);
        float4 bv = *(const float4*)(Wptr + (size_t)k0 * N);
        __syncthreads();  // previous iteration's compute done before overwrite
        As[acol + 0][arow] = av.x;
        As[acol + 1][arow] = av.y;
        As[acol + 2][arow] = av.z;
        As[acol + 3][arow] = av.w;
        *(float4*)&Bs[brow][bcol] = bv;
        __syncthreads();
#pragma unroll
        for (int kk = 0; kk < 8; kk++) {
            float a[8], b[8];
            *(float4*)(a)     = *(float4*)&As[kk][ty * 8];
            *(float4*)(a + 4) = *(float4*)&As[kk][ty * 8 + 4];
            *(float4*)(b)     = *(float4*)&Bs[kk][tx * 8];
            *(float4*)(b + 4) = *(float4*)&Bs[kk][tx * 8 + 4];
#pragma unroll
            for (int i = 0; i < 8; i++)
#pragma unroll
                for (int j = 0; j < 8; j++)
                    acc[i][j] += a[i] * b[j];
        }
    }
#pragma unroll
    for (int i = 0; i < 8; i++) {
        int row = bm + ty * 8 + i;
        float* crow = C + (size_t)row * N + bn + tx * 8;
#pragma unroll
        for (int j = 0; j < 8; j++) {
            float vv = acc[i][j] + bias[bn + tx * 8 + j];
            if (relu) vv = fmaxf(vv, 0.f);
            crow[j] = vv;
        }
    }
}

// ---------------- flash attention (fp32, online softmax) --------------------
// grid (S/32, H), 256 threads. 32 queries x 32-key tiles, HD=64.
// thread (r = tid/8, lane = tid%8): owns row r, dims lane*8..lane*8+7.
__global__ __launch_bounds__(256) void attn_kernel(
    const float* __restrict__ Q, const float* __restrict__ Kk,
    const float* __restrict__ V, float* __restrict__ O) {
    __shared__ float Qs[32][68];
    __shared__ float Ks[32][68];
    __shared__ float Vs[32][68];
    __shared__ float Ps[32][33];
    int h = blockIdx.y;
    int s0 = blockIdx.x * 32;
    int tid = threadIdx.x;
    int lrow = tid >> 3;       // loading row 0..31
    int lc0 = (tid & 7) * 8;   // loading col offset
    int r = tid >> 3;
    int lane = tid & 7;

    {
        const float* src = Q + (size_t)(s0 + lrow) * D + h * HD + lc0;
        *(float4*)&Qs[lrow][lc0]     = *(const float4*)(src);
        *(float4*)&Qs[lrow][lc0 + 4] = *(const float4*)(src + 4);
    }

    float m = -INFINITY, l = 0.f;
    float acc[8];
#pragma unroll
    for (int j = 0; j < 8; j++) acc[j] = 0.f;
    const float scale = 0.125f;  // 1/sqrt(64)

    for (int t0 = 0; t0 < S; t0 += 32) {
        __syncthreads();  // prev-iter reads of Ks/Vs done (also publishes Qs)
        {
            const float* ks = Kk + (size_t)(t0 + lrow) * D + h * HD + lc0;
            const float* vs = V  + (size_t)(t0 + lrow) * D + h * HD + lc0;
            *(float4*)&Ks[lrow][lc0]     = *(const float4*)(ks);
            *(float4*)&Ks[lrow][lc0 + 4] = *(const float4*)(ks + 4);
            *(float4*)&Vs[lrow][lc0]     = *(const float4*)(vs);
            *(float4*)&Vs[lrow][lc0 + 4] = *(const float4*)(vs + 4);
        }
        __syncthreads();

        float sc[4];
#pragma unroll
        for (int c4 = 0; c4 < 4; c4++) {
            int col = lane + c4 * 8;
            float sum = 0.f;
#pragma unroll
            for (int d = 0; d < 64; d += 4) {
                float4 qv = *(float4*)&Qs[r][d];
                float4 kv = *(float4*)&Ks[col][d];
                sum += qv.x * kv.x + qv.y * kv.y + qv.z * kv.z + qv.w * kv.w;
            }
            sc[c4] = sum * scale;
        }
        float tmax = fmaxf(fmaxf(sc[0], sc[1]), fmaxf(sc[2], sc[3]));
#pragma unroll
        for (int off = 1; off < 8; off <<= 1)
            tmax = fmaxf(tmax, __shfl_xor_sync(0xffffffffu, tmax, off));
        float newm = fmaxf(m, tmax);
        float corr = expf(m - newm);  // expf(-inf)=0 on first tile
        float psum = 0.f;
#pragma unroll
        for (int c4 = 0; c4 < 4; c4++) {
            float p = expf(sc[c4] - newm);
            Ps[r][lane + c4 * 8] = p;
            psum += p;
        }
#pragma unroll
        for (int off = 1; off < 8; off <<= 1)
            psum += __shfl_xor_sync(0xffffffffu, psum, off);
        l = l * corr + psum;
        m = newm;
#pragma unroll
        for (int j = 0; j < 8; j++) acc[j] *= corr;
        __syncwarp();  // Ps of row r written only by this row's 8 lanes (same warp)
#pragma unroll 4
        for (int c = 0; c < 32; c++) {
            float p = Ps[r][c];
            float4 v0 = *(float4*)&Vs[c][lane * 8];
            float4 v1 = *(float4*)&Vs[c][lane * 8 + 4];
            acc[0] += p * v0.x; acc[1] += p * v0.y;
            acc[2] += p * v0.z; acc[3] += p * v0.w;
            acc[4] += p * v1.x; acc[5] += p * v1.y;
            acc[6] += p * v1.z; acc[7] += p * v1.w;
        }
    }
    float inv = 1.f / l;
    float* dst = O + (size_t)(s0 + r) * D + h * HD + lane * 8;
#pragma unroll
    for (int j = 0; j < 8; j++) dst[j] = acc[j] * inv;
}

// ---------------- reductions ------------------------------------------------
__device__ __forceinline__ float block_sum256(float v, float* sbuf) {
    int tid = threadIdx.x;
#pragma unroll
    for (int off = 16; off > 0; off >>= 1)
        v += __shfl_xor_sync(0xffffffffu, v, off);
    if ((tid & 31) == 0) sbuf[tid >> 5] = v;
    __syncthreads();
    if (tid < 32) {
        float w = (tid < 8) ? sbuf[tid] : 0.f;
#pragma unroll
        for (int off = 4; off > 0; off >>= 1)
            w += __shfl_xor_sync(0xffffffffu, w, off);
        if (tid == 0) sbuf[0] = w;
    }
    __syncthreads();
    float r = sbuf[0];
    __syncthreads();  // safe reuse of sbuf
    return r;
}

// out = LayerNorm(x + res) * g + b   (row per block; two-pass variance)
__global__ __launch_bounds__(256) void addln_kernel(
    const float* __restrict__ x, const float* __restrict__ res,
    const float* __restrict__ g, const float* __restrict__ b,
    float* __restrict__ out) {
    __shared__ float sbuf[8];
    int s = blockIdx.x;
    int tid = threadIdx.x;
    float v[4];
    float loc = 0.f;
#pragma unroll
    for (int i = 0; i < 4; i++) {
        int d = tid + i * 256;
        v[i] = x[(size_t)s * D + d] + res[(size_t)s * D + d];
        loc += v[i];
    }
    float mean = block_sum256(loc, sbuf) * (1.f / D);
    float lv = 0.f;
#pragma unroll
    for (int i = 0; i < 4; i++) {
        float dd = v[i] - mean;
        lv += dd * dd;
    }
    float var = block_sum256(lv, sbuf) * (1.f / D);
    float rstd = rsqrtf(var + 1e-5f);
#pragma unroll
    for (int i = 0; i < 4; i++) {
        int d = tid + i * 256;
        out[(size_t)s * D + d] = (v[i] - mean) * rstd * g[d] + b[d];
    }
}

// logits[s] = h[s,:] . ws2 + bs2
__global__ __launch_bounds__(256) void logits_kernel(
    const float* __restrict__ hfeat, const float* __restrict__ w,
    const float* __restrict__ b, float* __restrict__ out) {
    __shared__ float sbuf[8];
    int s = blockIdx.x;
    int tid = threadIdx.x;
    float loc = 0.f;
#pragma unroll
    for (int i = 0; i < 4; i++) {
        int d = tid + i * 256;
        loc += hfeat[(size_t)s * MH + d] * w[d];
    }
    float total = block_sum256(loc, sbuf);
    if (tid == 0) out[s] = total + b[0];
}

// ---------------- launch ----------------------------------------------------
extern "C" void kernel_launch(void* const* d_in, const int* in_sizes, int n_in,
                              void* d_out, int out_size) {
    const float* node_emb = (const float*)d_in[0];
    const int*   tile_ids = (const int*)d_in[1];
    const int*   ny       = (const int*)d_in[2];
    const float* wq  = (const float*)d_in[3];
    const float* wk  = (const float*)d_in[4];
    const float* wv  = (const float*)d_in[5];
    const float* bq  = (const float*)d_in[6];
    const float* bk  = (const float*)d_in[7];
    const float* bv  = (const float*)d_in[8];
    const float* wo  = (const float*)d_in[9];
    const float* bo  = (const float*)d_in[10];
    const float* w1  = (const float*)d_in[11];
    const float* b1  = (const float*)d_in[12];
    const float* w2  = (const float*)d_in[13];
    const float* b2  = (const float*)d_in[14];
    const float* g1  = (const float*)d_in[15];
    const float* be1 = (const float*)d_in[16];
    const float* g2  = (const float*)d_in[17];
    const float* be2 = (const float*)d_in[18];
    const float* ws0 = (const float*)d_in[19];
    const float* bs0 = (const float*)d_in[20];
    const float* ws1 = (const float*)d_in[21];
    const float* bs1 = (const float*)d_in[22];
    const float* ws2 = (const float*)d_in[23];
    const float* bs2 = (const float*)d_in[24];
    float* out = (float*)d_out;

    float *x, *xr, *q, *k, *v, *ctx, *ff;
    cudaGetSymbolAddress((void**)&x,   g_x);
    cudaGetSymbolAddress((void**)&xr,  g_xr);
    cudaGetSymbolAddress((void**)&q,   g_q);
    cudaGetSymbolAddress((void**)&k,   g_k);
    cudaGetSymbolAddress((void**)&v,   g_v);
    cudaGetSymbolAddress((void**)&ctx, g_ctx);
    cudaGetSymbolAddress((void**)&ff,  g_ff);

    dim3 gDD(D / 128, S / 128);    // N=1024 gemms: (8,16)
    dim3 gDF(FF / 128, S / 128);   // N=2048 gemm:  (16,16)
    dim3 gAttn(S / 32, H);         // (64,16)

    gather_kernel<<<S, 256>>>(node_emb, tile_ids, x);

    for (int l = 0; l < L; l++) {
        const size_t oDD = (size_t)l * D * D;
        const size_t oD  = (size_t)l * D;
        const size_t oDF = (size_t)l * D * FF;
        const size_t oF  = (size_t)l * FF;

        rope_kernel<<<S, 256>>>(x, tile_ids, ny, xr);
        gemm_kernel<<<gDD, 256>>>(xr, wq + oDD, bq + oD, q, S, D, D, 0);
        gemm_kernel<<<gDD, 256>>>(xr, wk + oDD, bk + oD, k, S, D, D, 0);
        gemm_kernel<<<gDD, 256>>>(x,  wv + oDD, bv + oD, v, S, D, D, 0);
        attn_kernel<<<gAttn, 256>>>(q, k, v, ctx);
        gemm_kernel<<<gDD, 256>>>(ctx, wo + oDD, bo + oD, q, S, D, D, 0);
        addln_kernel<<<S, 256>>>(x, q, g1 + oD, be1 + oD, x);
        gemm_kernel<<<gDF, 256>>>(x, w1 + oDF, b1 + oF, ff, S, FF, D, 1);
        gemm_kernel<<<gDD, 256>>>(ff, w2 + (size_t)l * FF * D, b2 + oD, q,
                                  S, D, FF, 0);
        addln_kernel<<<S, 256>>>(x, q, g2 + oD, be2 + oD, x);
    }

    gemm_kernel<<<gDD, 256>>>(x, ws0, bs0, q, S, MH, D, 1);
    gemm_kernel<<<gDD, 256>>>(q, ws1, bs1, k, S, MH, MH, 1);
    logits_kernel<<<S, 256>>>(k, ws2, bs2, out);
}

// round 4
// speedup vs baseline: 1.3121x; 1.3121x over previous
#include <cuda_runtime.h>
#include <cuda_bf16.h>
#include <math.h>
#include <stdint.h>

#define S  2048
#define D  1024
#define H  16
#define HD 64
#define L  2
#define MH 1024
#define FF (2 * D)

// ---------------- scratch (device globals; no allocation allowed) ----------
__device__ float g_x[S * D];
__device__ float g_xr[S * D];
__device__ float g_q[S * D];
__device__ float g_k[S * D];
__device__ float g_v[S * D];
__device__ float g_ctx[S * D];
__device__ float g_ff[S * FF];

// bf16x3 expanded operands
// per layer: wq,wk,wv,wo: [1024 x 3072]; w1: [2048 x 3072]; w2: [1024 x 6144]
#define PER_LAYER 25165824ll
#define WQo 0ll
#define WKo 3145728ll
#define WVo 6291456ll
#define WOo 9437184ll
#define W1o 12582912ll
#define W2o 18874368ll
#define WS0o (2ll * PER_LAYER)
#define WS1o (WS0o + 3145728ll)
__device__ __nv_bfloat16 g_wext[56623104ll];
__device__ __nv_bfloat16 g_aext[(size_t)S * 6144];

// ==================== PTX helpers (Ampere-era only) =========================
__device__ __forceinline__ uint32_t smem_u32(const void* p) {
    return (uint32_t)__cvta_generic_to_shared(p);
}
__device__ __forceinline__ void cp_async16(uint32_t s, const void* g) {
    asm volatile("cp.async.cg.shared.global [%0], [%1], 16;" :: "r"(s), "l"(g));
}
__device__ __forceinline__ void ldsm4(uint32_t* r, uint32_t addr) {
    asm volatile("ldmatrix.sync.aligned.m8n8.x4.shared.b16 {%0,%1,%2,%3}, [%4];"
                 : "=r"(r[0]), "=r"(r[1]), "=r"(r[2]), "=r"(r[3]) : "r"(addr));
}
__device__ __forceinline__ void mma16816(float* c, const uint32_t* a,
                                         const uint32_t* b) {
    asm volatile(
        "mma.sync.aligned.m16n8k16.row.col.f32.bf16.bf16.f32 "
        "{%0,%1,%2,%3}, {%4,%5,%6,%7}, {%8,%9}, {%0,%1,%2,%3};"
        : "+f"(c[0]), "+f"(c[1]), "+f"(c[2]), "+f"(c[3])
        : "r"(a[0]), "r"(a[1]), "r"(a[2]), "r"(a[3]), "r"(b[0]), "r"(b[1]));
}

// ==================== conversion kernels ====================================
// W [K,N] fp32 -> Wext [N, 3K] bf16 : [hi | lo | hi]
__global__ void convert_w(const float* __restrict__ W, __nv_bfloat16* __restrict__ dst,
                          int K, int N) {
    __shared__ float t[32][33];
    int k0 = blockIdx.y * 32, n0 = blockIdx.x * 32;
    int tx = threadIdx.x, ty = threadIdx.y;
    for (int i = ty; i < 32; i += 8)
        t[i][tx] = W[(size_t)(k0 + i) * N + n0 + tx];
    __syncthreads();
    size_t K3 = 3 * (size_t)K;
    for (int i = ty; i < 32; i += 8) {
        int n = n0 + i, k = k0 + tx;
        float v = t[tx][i];
        __nv_bfloat16 hi = __float2bfloat16(v);
        __nv_bfloat16 lo = __float2bfloat16(v - __bfloat162float(hi));
        __nv_bfloat16* row = dst + (size_t)n * K3;
        row[k] = hi;
        row[K + k] = lo;
        row[2 * K + k] = hi;
    }
}

// A [M,K] fp32 -> Aext [M, 3K] bf16 : [hi | hi | lo]
__global__ void convert_a(const float* __restrict__ A, __nv_bfloat16* __restrict__ dst,
                          int K) {
    int m = blockIdx.y;
    int k = blockIdx.x * 256 + threadIdx.x;
    float v = A[(size_t)m * K + k];
    __nv_bfloat16 hi = __float2bfloat16(v);
    __nv_bfloat16 lo = __float2bfloat16(v - __bfloat162float(hi));
    __nv_bfloat16* row = dst + (size_t)m * 3 * (size_t)K;
    row[k] = hi;
    row[K + k] = hi;
    row[2 * K + k] = lo;
}

// ==================== mma.sync GEMM =========================================
// C[M,N] = Aext[M,K3] x Wext[N,K3]^T + bias (opt relu). fp32 out.
// 128x128 CTA tile, 256 threads (8 warps: 4 along M x 2 along N),
// warp tile 32x64, BK=32, cp.async double buffer, rows padded to 80B.
// SMEM: buf b at b*20480: A[128][40] bf16 then B[128][40] bf16.
__global__ __launch_bounds__(256) void gemm_mma(
    const __nv_bfloat16* __restrict__ A, const __nv_bfloat16* __restrict__ B,
    const float* __restrict__ bias, float* __restrict__ C,
    int N, int K3, int relu) {
    __shared__ __align__(16) char smem[40960];
    int tid = threadIdx.x;
    int bm = blockIdx.y * 128, bn = blockIdx.x * 128;
    int wid = tid >> 5, lane = tid & 31;
    int m0 = (wid & 3) * 32;     // warp M offset
    int n0 = (wid >> 2) * 64;    // warp N offset
    uint32_t sbase = smem_u32(smem);

    // --- stage addressing: thread loads 2x16B for A and 2x16B for B ---
    int lrow = tid >> 1;
    int lsub = (tid & 1) * 2;   // 16B segs lsub, lsub+1 of 4
    const char* gA = (const char*)(A + (size_t)(bm + lrow) * K3) + lsub * 16;
    const char* gB = (const char*)(B + (size_t)(bn + lrow) * K3) + lsub * 16;
    uint32_t sA = sbase + (uint32_t)lrow * 80u + (uint32_t)lsub * 16u;
    uint32_t sB = sbase + 10240u + (uint32_t)lrow * 80u + (uint32_t)lsub * 16u;

    // --- ldmatrix lane addressing ---
    int a_r = (lane & 7) + ((lane >> 3) & 1) * 8;
    int a_k = (lane >> 4) * 16;                     // bytes
    int b_r = (lane & 7) + ((lane >> 4) & 1) * 8;
    int b_k = ((lane >> 3) & 1) * 16;
    uint32_t aAddr[2], bAddr[4];
#pragma unroll
    for (int mt = 0; mt < 2; mt++)
        aAddr[mt] = sbase + (uint32_t)(m0 + mt * 16 + a_r) * 80u + a_k;
#pragma unroll
    for (int p = 0; p < 4; p++)
        bAddr[p] = sbase + 10240u + (uint32_t)(n0 + p * 16 + b_r) * 80u + b_k;

    float acc[2][8][4];
#pragma unroll
    for (int mt = 0; mt < 2; mt++)
#pragma unroll
        for (int nt = 0; nt < 8; nt++)
#pragma unroll
            for (int e = 0; e < 4; e++) acc[mt][nt][e] = 0.f;

#define PF(kc, buf)                                                           \
    {                                                                         \
        const char* pa = gA + (size_t)(kc) * 64;                              \
        const char* pb = gB + (size_t)(kc) * 64;                              \
        uint32_t da = sA + (buf) * 20480u;                                    \
        uint32_t db = sB + (buf) * 20480u;                                    \
        cp_async16(da, pa);                                                   \
        cp_async16(da + 16, pa + 16);                                         \
        cp_async16(db, pb);                                                   \
        cp_async16(db + 16, pb + 16);                                         \
        asm volatile("cp.async.commit_group;" ::: "memory");                  \
    }

    int NC = K3 >> 5;
    PF(0, 0);
    for (int c = 0; c < NC; c++) {
        int b = c & 1;
        if (c + 1 < NC) {
            PF(c + 1, b ^ 1);
            asm volatile("cp.async.wait_group 1;" ::: "memory");
        } else {
            asm volatile("cp.async.wait_group 0;" ::: "memory");
        }
        __syncthreads();
        uint32_t boff = (uint32_t)b * 20480u;
#pragma unroll
        for (int h = 0; h < 2; h++) {
            uint32_t koff = boff + (uint32_t)h * 32u;
            uint32_t afr[2][4];
            ldsm4(afr[0], aAddr[0] + koff);
            ldsm4(afr[1], aAddr[1] + koff);
            uint32_t bfr[8][2];
#pragma unroll
            for (int p = 0; p < 4; p++) {
                uint32_t r[4];
                ldsm4(r, bAddr[p] + koff);
                bfr[2 * p][0] = r[0];
                bfr[2 * p][1] = r[1];
                bfr[2 * p + 1][0] = r[2];
                bfr[2 * p + 1][1] = r[3];
            }
#pragma unroll
            for (int mt = 0; mt < 2; mt++)
#pragma unroll
                for (int nt = 0; nt < 8; nt++)
                    mma16816(acc[mt][nt], afr[mt], bfr[nt]);
        }
        __syncthreads();
    }
#undef PF

    // --- epilogue: C fragment thread mapping ---
    int cr = lane >> 2;           // 0..7
    int cc = (lane & 3) * 2;      // 0,2,4,6
#pragma unroll
    for (int mt = 0; mt < 2; mt++) {
#pragma unroll
        for (int nt = 0; nt < 8; nt++) {
            int col = bn + n0 + nt * 8 + cc;
            float bx = bias[col], by = bias[col + 1];
            int row = bm + m0 + mt * 16 + cr;
            float2 v0, v1;
            v0.x = acc[mt][nt][0] + bx;
            v0.y = acc[mt][nt][1] + by;
            v1.x = acc[mt][nt][2] + bx;
            v1.y = acc[mt][nt][3] + by;
            if (relu) {
                v0.x = fmaxf(v0.x, 0.f); v0.y = fmaxf(v0.y, 0.f);
                v1.x = fmaxf(v1.x, 0.f); v1.y = fmaxf(v1.y, 0.f);
            }
            *(float2*)(C + (size_t)row * N + col) = v0;
            *(float2*)(C + (size_t)(row + 8) * N + col) = v1;
        }
    }
}

// ==================== gather / rope =========================================
__global__ void gather_kernel(const float* __restrict__ emb,
                              const int* __restrict__ ids,
                              float* __restrict__ x) {
    int s = blockIdx.x;
    int id = ids[s];
    const float4* src = (const float4*)(emb + (size_t)id * D);
    float4* dst = (float4*)(x + (size_t)s * D);
    dst[threadIdx.x] = src[threadIdx.x];
}

__global__ void rope_kernel(const float* __restrict__ x,
                            const int* __restrict__ ids,
                            const int* __restrict__ nyp,
                            float* __restrict__ xr) {
    int s = blockIdx.x;
    int j = threadIdx.x;  // 0..255
    int id = ids[s];
    int Ny = nyp[0];
    float rowp = (float)(id / Ny);
    float colp = (float)(id % Ny);
    float theta = powf(10000.f, -((float)j) * (1.f / 256.f));
    float a1 = rowp * theta;
    float a2 = colp * theta;
    float s1, c1, s2, c2;
    sincosf(a1, &s1, &c1);
    sincosf(a2, &s2, &c2);
    const float* xs = x + (size_t)s * D;
    float* xd = xr + (size_t)s * D;
    float x1 = xs[j], x2 = xs[j + 256];
    xd[j]       = x1 * c1 - x2 * s1;
    xd[j + 256] = x1 * s1 + x2 * c1;
    float y1 = xs[j + 512], y2 = xs[j + 768];
    xd[j + 512] = y1 * c2 - y2 * s2;
    xd[j + 768] = y1 * s2 + y2 * c2;
}

// ==================== flash attention (fp32, Q in regs) =====================
__global__ __launch_bounds__(256, 2) void attn_kernel(
    const float* __restrict__ Q, const float* __restrict__ Kk,
    const float* __restrict__ V, float* __restrict__ O) {
    __shared__ float Qs[32][68];
    __shared__ float Ks[32][68];
    __shared__ float Vs[32][68];
    __shared__ float Ps[32][33];
    int h = blockIdx.y;
    int s0 = blockIdx.x * 32;
    int tid = threadIdx.x;
    int lrow = tid >> 3;
    int lc0 = (tid & 7) * 8;
    int r = tid >> 3;
    int lane = tid & 7;

    {
        const float* src = Q + (size_t)(s0 + lrow) * D + h * HD + lc0;
        *(float4*)&Qs[lrow][lc0]     = *(const float4*)(src);
        *(float4*)&Qs[lrow][lc0 + 4] = *(const float4*)(src + 4);
    }
    __syncthreads();
    float qr[64];
#pragma unroll
    for (int d = 0; d < 64; d += 4)
        *(float4*)&qr[d] = *(float4*)&Qs[r][d];

    float m = -INFINITY, l = 0.f;
    float acc[8];
#pragma unroll
    for (int j = 0; j < 8; j++) acc[j] = 0.f;
    const float scale = 0.125f;

    for (int t0 = 0; t0 < S; t0 += 32) {
        __syncthreads();
        {
            const float* ks = Kk + (size_t)(t0 + lrow) * D + h * HD + lc0;
            const float* vs = V  + (size_t)(t0 + lrow) * D + h * HD + lc0;
            *(float4*)&Ks[lrow][lc0]     = *(const float4*)(ks);
            *(float4*)&Ks[lrow][lc0 + 4] = *(const float4*)(ks + 4);
            *(float4*)&Vs[lrow][lc0]     = *(const float4*)(vs);
            *(float4*)&Vs[lrow][lc0 + 4] = *(const float4*)(vs + 4);
        }
        __syncthreads();

        float sc[4];
#pragma unroll
        for (int c4 = 0; c4 < 4; c4++) {
            int col = lane + c4 * 8;
            float sum = 0.f;
#pragma unroll
            for (int d = 0; d < 64; d += 4) {
                float4 kv = *(float4*)&Ks[col][d];
                sum += qr[d] * kv.x + qr[d + 1] * kv.y +
                       qr[d + 2] * kv.z + qr[d + 3] * kv.w;
            }
            sc[c4] = sum * scale;
        }
        float tmax = fmaxf(fmaxf(sc[0], sc[1]), fmaxf(sc[2], sc[3]));
#pragma unroll
        for (int off = 1; off < 8; off <<= 1)
            tmax = fmaxf(tmax, __shfl_xor_sync(0xffffffffu, tmax, off));
        float newm = fmaxf(m, tmax);
        float corr = expf(m - newm);
        float psum = 0.f;
#pragma unroll
        for (int c4 = 0; c4 < 4; c4++) {
            float p = expf(sc[c4] - newm);
            Ps[r][lane + c4 * 8] = p;
            psum += p;
        }
#pragma unroll
        for (int off = 1; off < 8; off <<= 1)
            psum += __shfl_xor_sync(0xffffffffu, psum, off);
        l = l * corr + psum;
        m = newm;
#pragma unroll
        for (int j = 0; j < 8; j++) acc[j] *= corr;
        __syncwarp();
#pragma unroll 4
        for (int c = 0; c < 32; c++) {
            float p = Ps[r][c];
            float4 v0 = *(float4*)&Vs[c][lane * 8];
            float4 v1 = *(float4*)&Vs[c][lane * 8 + 4];
            acc[0] += p * v0.x; acc[1] += p * v0.y;
            acc[2] += p * v0.z; acc[3] += p * v0.w;
            acc[4] += p * v1.x; acc[5] += p * v1.y;
            acc[6] += p * v1.z; acc[7] += p * v1.w;
        }
    }
    float inv = 1.f / l;
    float* dst = O + (size_t)(s0 + r) * D + h * HD + lane * 8;
#pragma unroll
    for (int j = 0; j < 8; j++) dst[j] = acc[j] * inv;
}

// ==================== layernorm / logits ====================================
__device__ __forceinline__ float block_sum256(float v, float* sbuf) {
    int tid = threadIdx.x;
#pragma unroll
    for (int off = 16; off > 0; off >>= 1)
        v += __shfl_xor_sync(0xffffffffu, v, off);
    if ((tid & 31) == 0) sbuf[tid >> 5] = v;
    __syncthreads();
    if (tid < 32) {
        float w = (tid < 8) ? sbuf[tid] : 0.f;
#pragma unroll
        for (int off = 4; off > 0; off >>= 1)
            w += __shfl_xor_sync(0xffffffffu, w, off);
        if (tid == 0) sbuf[0] = w;
    }
    __syncthreads();
    float r = sbuf[0];
    __syncthreads();
    return r;
}

__global__ __launch_bounds__(256) void addln_kernel(
    const float* __restrict__ x, const float* __restrict__ res,
    const float* __restrict__ g, const float* __restrict__ b,
    float* __restrict__ out) {
    __shared__ float sbuf[8];
    int s = blockIdx.x;
    int tid = threadIdx.x;
    float v[4];
    float loc = 0.f;
#pragma unroll
    for (int i = 0; i < 4; i++) {
        int d = tid + i * 256;
        v[i] = x[(size_t)s * D + d] + res[(size_t)s * D + d];
        loc += v[i];
    }
    float mean = block_sum256(loc, sbuf) * (1.f / D);
    float lv = 0.f;
#pragma unroll
    for (int i = 0; i < 4; i++) {
        float dd = v[i] - mean;
        lv += dd * dd;
    }
    float var = block_sum256(lv, sbuf) * (1.f / D);
    float rstd = rsqrtf(var + 1e-5f);
#pragma unroll
    for (int i = 0; i < 4; i++) {
        int d = tid + i * 256;
        out[(size_t)s * D + d] = (v[i] - mean) * rstd * g[d] + b[d];
    }
}

__global__ __launch_bounds__(256) void logits_kernel(
    const float* __restrict__ hfeat, const float* __restrict__ w,
    const float* __restrict__ b, float* __restrict__ out) {
    __shared__ float sbuf[8];
    int s = blockIdx.x;
    int tid = threadIdx.x;
    float loc = 0.f;
#pragma unroll
    for (int i = 0; i < 4; i++) {
        int d = tid + i * 256;
        loc += hfeat[(size_t)s * MH + d] * w[d];
    }
    float total = block_sum256(loc, sbuf);
    if (tid == 0) out[s] = total + b[0];
}

// ==================== launch ================================================
extern "C" void kernel_launch(void* const* d_in, const int* in_sizes, int n_in,
                              void* d_out, int out_size) {
    const float* node_emb = (const float*)d_in[0];
    const int*   tile_ids = (const int*)d_in[1];
    const int*   ny       = (const int*)d_in[2];
    const float* wq  = (const float*)d_in[3];
    const float* wk  = (const float*)d_in[4];
    const float* wv  = (const float*)d_in[5];
    const float* bq  = (const float*)d_in[6];
    const float* bk  = (const float*)d_in[7];
    const float* bv  = (const float*)d_in[8];
    const float* wo  = (const float*)d_in[9];
    const float* bo  = (const float*)d_in[10];
    const float* w1  = (const float*)d_in[11];
    const float* b1  = (const float*)d_in[12];
    const float* w2  = (const float*)d_in[13];
    const float* b2  = (const float*)d_in[14];
    const float* g1  = (const float*)d_in[15];
    const float* be1 = (const float*)d_in[16];
    const float* g2  = (const float*)d_in[17];
    const float* be2 = (const float*)d_in[18];
    const float* ws0 = (const float*)d_in[19];
    const float* bs0 = (const float*)d_in[20];
    const float* ws1 = (const float*)d_in[21];
    const float* bs1 = (const float*)d_in[22];
    const float* ws2 = (const float*)d_in[23];
    const float* bs2 = (const float*)d_in[24];
    float* out = (float*)d_out;

    float *x, *xr, *q, *k, *v, *ctx, *ff;
    __nv_bfloat16 *wext, *aext;
    cudaGetSymbolAddress((void**)&x,    g_x);
    cudaGetSymbolAddress((void**)&xr,   g_xr);
    cudaGetSymbolAddress((void**)&q,    g_q);
    cudaGetSymbolAddress((void**)&k,    g_k);
    cudaGetSymbolAddress((void**)&v,    g_v);
    cudaGetSymbolAddress((void**)&ctx,  g_ctx);
    cudaGetSymbolAddress((void**)&ff,   g_ff);
    cudaGetSymbolAddress((void**)&wext, g_wext);
    cudaGetSymbolAddress((void**)&aext, g_aext);

    dim3 cw8(32, 8);
    // weight conversion: W[K,N] -> Wext[N,3K]
    for (int l = 0; l < L; l++) {
        long long off = (long long)l * PER_LAYER;
        convert_w<<<dim3(D / 32, D / 32), cw8>>>(wq + (size_t)l * D * D, wext + off + WQo, D, D);
        convert_w<<<dim3(D / 32, D / 32), cw8>>>(wk + (size_t)l * D * D, wext + off + WKo, D, D);
        convert_w<<<dim3(D / 32, D / 32), cw8>>>(wv + (size_t)l * D * D, wext + off + WVo, D, D);
        convert_w<<<dim3(D / 32, D / 32), cw8>>>(wo + (size_t)l * D * D, wext + off + WOo, D, D);
        convert_w<<<dim3(FF / 32, D / 32), cw8>>>(w1 + (size_t)l * D * FF, wext + off + W1o, D, FF);
        convert_w<<<dim3(D / 32, FF / 32), cw8>>>(w2 + (size_t)l * FF * D, wext + off + W2o, FF, D);
    }
    convert_w<<<dim3(MH / 32, D / 32), cw8>>>(ws0, wext + WS0o, D, MH);
    convert_w<<<dim3(MH / 32, MH / 32), cw8>>>(ws1, wext + WS1o, MH, MH);

    dim3 gDD(D / 128, S / 128);
    dim3 gDF(FF / 128, S / 128);
    dim3 gAttn(S / 32, H);
    dim3 gCA(D / 256, S);
    dim3 gCAF(FF / 256, S);

    gather_kernel<<<S, 256>>>(node_emb, tile_ids, x);

    for (int l = 0; l < L; l++) {
        long long woff = (long long)l * PER_LAYER;
        const size_t oD = (size_t)l * D;
        const size_t oF = (size_t)l * FF;

        rope_kernel<<<S, 256>>>(x, tile_ids, ny, xr);
        convert_a<<<gCA, 256>>>(xr, aext, D);
        gemm_mma<<<gDD, 256>>>(aext, wext + woff + WQo, bq + oD, q, D, 3 * D, 0);
        gemm_mma<<<gDD, 256>>>(aext, wext + woff + WKo, bk + oD, k, D, 3 * D, 0);
        convert_a<<<gCA, 256>>>(x, aext, D);
        gemm_mma<<<gDD, 256>>>(aext, wext + woff + WVo, bv + oD, v, D, 3 * D, 0);
        attn_kernel<<<gAttn, 256>>>(q, k, v, ctx);
        convert_a<<<gCA, 256>>>(ctx, aext, D);
        gemm_mma<<<gDD, 256>>>(aext, wext + woff + WOo, bo + oD, q, D, 3 * D, 0);
        addln_kernel<<<S, 256>>>(x, q, g1 + oD, be1 + oD, x);
        convert_a<<<gCA, 256>>>(x, aext, D);
        gemm_mma<<<gDF, 256>>>(aext, wext + woff + W1o, b1 + oF, ff, FF, 3 * D, 1);
        convert_a<<<gCAF, 256>>>(ff, aext, FF);
        gemm_mma<<<gDD, 256>>>(aext, wext + woff + W2o, b2 + oD, q, D, 3 * FF, 0);
        addln_kernel<<<S, 256>>>(x, q, g2 + oD, be2 + oD, x);
    }

    convert_a<<<gCA, 256>>>(x, aext, D);
    gemm_mma<<<gDD, 256>>>(aext, wext + WS0o, bs0, q, MH, 3 * D, 1);
    convert_a<<<gCA, 256>>>(q, aext, MH);
    gemm_mma<<<gDD, 256>>>(aext, wext + WS1o, bs1, k, MH, 3 * MH, 1);
    logits_kernel<<<S, 256>>>(k, ws2, bs2, out);
}

// round 5
// speedup vs baseline: 1.3225x; 1.0080x over previous
#include <cuda_runtime.h>
#include <cuda_bf16.h>
#include <math.h>
#include <stdint.h>

#define S  2048
#define D  1024
#define H  16
#define HD 64
#define L  2
#define MH 1024
#define FF 2048

// ---------------- scratch (device globals) ----------------------------------
__device__ float g_x[S * D];          // residual stream (fp32)
__device__ float g_qk[S * 2048];      // fused q|k output
__device__ float g_v[S * D];
__device__ float g_tmp[S * D];        // attn_out / ff2 out / head h2
__device__ float g_bias2[2048];       // concat bq|bk
// bf16x3 weights: wq,wk,wv,wo: [1024 x 3072]; w1: [2048 x 3072]; w2: [1024 x 6144]
#define PER_LAYER 25165824ll
#define WQo 0ll
#define WKo 3145728ll
#define WVo 6291456ll
#define WOo 9437184ll
#define W1o 12582912ll
#define W2o 18874368ll
#define WS0o (2ll * PER_LAYER)
#define WS1o (WS0o + 3145728ll)
__device__ __nv_bfloat16 g_wext[56623104ll];
__device__ __nv_bfloat16 g_aextA[(size_t)S * 6144];  // roped-x / ctx / ff ext
__device__ __nv_bfloat16 g_aextB[(size_t)S * 6144];  // x ext

// ==================== PTX helpers ===========================================
__device__ __forceinline__ uint32_t smem_u32(const void* p) {
    return (uint32_t)__cvta_generic_to_shared(p);
}
__device__ __forceinline__ void cp_async16(uint32_t s, const void* g) {
    asm volatile("cp.async.cg.shared.global [%0], [%1], 16;" :: "r"(s), "l"(g));
}
__device__ __forceinline__ void ldsm4(uint32_t* r, uint32_t addr) {
    asm volatile("ldmatrix.sync.aligned.m8n8.x4.shared.b16 {%0,%1,%2,%3}, [%4];"
                 : "=r"(r[0]), "=r"(r[1]), "=r"(r[2]), "=r"(r[3]) : "r"(addr));
}
__device__ __forceinline__ void mma16816(float* c, const uint32_t* a,
                                         const uint32_t* b) {
    asm volatile(
        "mma.sync.aligned.m16n8k16.row.col.f32.bf16.bf16.f32 "
        "{%0,%1,%2,%3}, {%4,%5,%6,%7}, {%8,%9}, {%0,%1,%2,%3};"
        : "+f"(c[0]), "+f"(c[1]), "+f"(c[2]), "+f"(c[3])
        : "r"(a[0]), "r"(a[1]), "r"(a[2]), "r"(a[3]), "r"(b[0]), "r"(b[1]));
}
__device__ __forceinline__ void ext3_store2(__nv_bfloat16* row, int N, int col,
                                            float v0, float v1) {
    __nv_bfloat162 h2, l2;
    h2.x = __float2bfloat16(v0);
    h2.y = __float2bfloat16(v1);
    l2.x = __float2bfloat16(v0 - __bfloat162float(h2.x));
    l2.y = __float2bfloat16(v1 - __bfloat162float(h2.y));
    *(__nv_bfloat162*)(row + col) = h2;
    *(__nv_bfloat162*)(row + N + col) = h2;
    *(__nv_bfloat162*)(row + 2 * N + col) = l2;
}

// ==================== weight conversion =====================================
// W [K,N] fp32 -> Wext [N, 3K] bf16 : [hi | lo | hi]
__global__ void convert_w(const float* __restrict__ W,
                          __nv_bfloat16* __restrict__ dst, int K, int N) {
    __shared__ float t[32][33];
    int k0 = blockIdx.y * 32, n0 = blockIdx.x * 32;
    int tx = threadIdx.x, ty = threadIdx.y;
    for (int i = ty; i < 32; i += 8)
        t[i][tx] = W[(size_t)(k0 + i) * N + n0 + tx];
    __syncthreads();
    size_t K3 = 3 * (size_t)K;
    for (int i = ty; i < 32; i += 8) {
        int n = n0 + i, k = k0 + tx;
        float v = t[tx][i];
        __nv_bfloat16 hi = __float2bfloat16(v);
        __nv_bfloat16 lo = __float2bfloat16(v - __bfloat162float(hi));
        __nv_bfloat16* row = dst + (size_t)n * K3;
        row[k] = hi;
        row[K + k] = lo;
        row[2 * K + k] = hi;
    }
}

__global__ void concat_bias(const float* __restrict__ a,
                            const float* __restrict__ b,
                            float* __restrict__ o) {
    int t = blockIdx.x * 256 + threadIdx.x;
    o[t] = (t < 1024) ? a[t] : b[t - 1024];
}

// ==================== gather (+ext) =========================================
__global__ void gather_ext(const float* __restrict__ emb,
                           const int* __restrict__ ids,
                           float* __restrict__ x,
                           __nv_bfloat16* __restrict__ e) {
    int s = blockIdx.x, t = threadIdx.x;
    int id = ids[s];
    float4 v = ((const float4*)(emb + (size_t)id * D))[t];
    ((float4*)(x + (size_t)s * D))[t] = v;
    __nv_bfloat16* row = e + (size_t)s * 3072;
    int d = t * 4;
    ext3_store2(row, D, d, v.x, v.y);
    ext3_store2(row, D, d + 2, v.z, v.w);
}

// ==================== 2D RoPE (+ext, no fp32 out) ===========================
__global__ void rope_ext(const float* __restrict__ x,
                         const int* __restrict__ ids,
                         const int* __restrict__ nyp,
                         __nv_bfloat16* __restrict__ e) {
    int s = blockIdx.x;
    int j = threadIdx.x;  // 0..255
    int id = ids[s];
    int Ny = nyp[0];
    float rowp = (float)(id / Ny);
    float colp = (float)(id % Ny);
    float theta = powf(10000.f, -((float)j) * (1.f / 256.f));
    float s1, c1, s2, c2;
    sincosf(rowp * theta, &s1, &c1);
    sincosf(colp * theta, &s2, &c2);
    const float* xs = x + (size_t)s * D;
    __nv_bfloat16* row = e + (size_t)s * 3072;
    float x1 = xs[j], x2 = xs[j + 256];
    float y1 = xs[j + 512], y2 = xs[j + 768];
    float o0 = x1 * c1 - x2 * s1;
    float o1 = x1 * s1 + x2 * c1;
    float o2 = y1 * c2 - y2 * s2;
    float o3 = y1 * s2 + y2 * c2;
#define E1(d, v)                                                     \
    {                                                                \
        __nv_bfloat16 hi = __float2bfloat16(v);                      \
        row[d] = hi;                                                 \
        row[1024 + (d)] = hi;                                        \
        row[2048 + (d)] = __float2bfloat16((v) - __bfloat162float(hi)); \
    }
    E1(j, o0)
    E1(j + 256, o1)
    E1(j + 512, o2)
    E1(j + 768, o3)
#undef E1
}

// ==================== mma.sync GEMM, 3-stage pipeline =======================
// C[M,N] = Aext[M,K3] x Wext[N,K3]^T + bias.
// mode 0: fp32 C; 1: fp32 C + relu; 2: ext E + relu; 3: ext E.
// 128x128 CTA tile, 256 thr (8 warps 4Mx2N, warp 32x64), BK=32.
// smem: 3 stages x (A 128x64B + B 128x64B) = 49152B; seg-swizzle s^=(row&3).
#define STG 16384
__global__ __launch_bounds__(256) void gemm_mma(
    const __nv_bfloat16* __restrict__ A, const __nv_bfloat16* __restrict__ B,
    const float* __restrict__ bias, float* __restrict__ C,
    __nv_bfloat16* __restrict__ E, int N, int K3, int mode) {
    __shared__ __align__(16) char smem[49152];
    int tid = threadIdx.x;
    int bm = blockIdx.y * 128, bn = blockIdx.x * 128;
    int wid = tid >> 5, lane = tid & 31;
    int m0 = (wid & 3) * 32, n0 = (wid >> 2) * 64;
    uint32_t sb = smem_u32(smem);

    // staging: thread -> row lrow, segs lsub,lsub+1 (16B each)
    int lrow = tid >> 1, lsub = (tid & 1) * 2;
    const char* gA = (const char*)(A + (size_t)(bm + lrow) * K3);
    const char* gB = (const char*)(B + (size_t)(bn + lrow) * K3);
    uint32_t rowOff = (uint32_t)lrow * 64u;
    uint32_t swA0 = (uint32_t)((lsub ^ (lrow & 3)) * 16);
    uint32_t swA1 = (uint32_t)(((lsub + 1) ^ (lrow & 3)) * 16);

#define PF(kc, st)                                                     \
    {                                                                  \
        const char* pa = gA + (size_t)(kc) * 64 + lsub * 16;           \
        const char* pb = gB + (size_t)(kc) * 64 + lsub * 16;           \
        uint32_t ba = sb + (uint32_t)(st) * STG + rowOff;              \
        uint32_t bb = ba + 8192u;                                      \
        cp_async16(ba + swA0, pa);                                     \
        cp_async16(ba + swA1, pa + 16);                                \
        cp_async16(bb + swA0, pb);                                     \
        cp_async16(bb + swA1, pb + 16);                                \
        asm volatile("cp.async.commit_group;" ::: "memory");           \
    }

    // ldmatrix lane addressing (same fragment mapping as validated R4 kernel)
    int a_r = (lane & 7) + ((lane >> 3) & 1) * 8;
    int a_s = lane >> 4;            // 0/1
    int b_r = (lane & 7) + ((lane >> 4) & 1) * 8;
    int b_s = (lane >> 3) & 1;      // 0/1
    uint32_t aRow[2]; int aSw[2];
#pragma unroll
    for (int mt = 0; mt < 2; mt++) {
        int row = m0 + mt * 16 + a_r;
        aRow[mt] = (uint32_t)row * 64u;
        aSw[mt] = row & 3;
    }
    uint32_t bRow[4]; int bSw[4];
#pragma unroll
    for (int p = 0; p < 4; p++) {
        int row = n0 + p * 16 + b_r;
        bRow[p] = (uint32_t)row * 64u;
        bSw[p] = row & 3;
    }

    float acc[2][8][4];
#pragma unroll
    for (int mt = 0; mt < 2; mt++)
#pragma unroll
        for (int nt = 0; nt < 8; nt++)
#pragma unroll
            for (int e = 0; e < 4; e++) acc[mt][nt][e] = 0.f;

    int NC = K3 >> 5;
    PF(0, 0)
    PF(1, 1)
    int st = 0;
    for (int c = 0; c < NC; c++) {
        if (c + 1 < NC)
            asm volatile("cp.async.wait_group 1;" ::: "memory");
        else
            asm volatile("cp.async.wait_group 0;" ::: "memory");
        __syncthreads();
        if (c + 2 < NC) {
            int s2 = st + 2;
            if (s2 >= 3) s2 -= 3;
            PF(c + 2, s2)
        }
        uint32_t base = sb + (uint32_t)st * STG;
#pragma unroll
        for (int h = 0; h < 2; h++) {
            uint32_t afr[2][4];
#pragma unroll
            for (int mt = 0; mt < 2; mt++)
                ldsm4(afr[mt], base + aRow[mt] +
                                   (uint32_t)(((a_s + 2 * h) ^ aSw[mt]) * 16));
            uint32_t bfr[8][2];
#pragma unroll
            for (int p = 0; p < 4; p++) {
                uint32_t r[4];
                ldsm4(r, base + 8192u + bRow[p] +
                             (uint32_t)(((b_s + 2 * h) ^ bSw[p]) * 16));
                bfr[2 * p][0] = r[0];
                bfr[2 * p][1] = r[1];
                bfr[2 * p + 1][0] = r[2];
                bfr[2 * p + 1][1] = r[3];
            }
#pragma unroll
            for (int mt = 0; mt < 2; mt++)
#pragma unroll
                for (int nt = 0; nt < 8; nt++)
                    mma16816(acc[mt][nt], afr[mt], bfr[nt]);
        }
        st = (st == 2) ? 0 : st + 1;
    }
#undef PF

    int cr = lane >> 2;           // 0..7
    int cc = (lane & 3) * 2;      // 0,2,4,6
    if (mode <= 1) {
#pragma unroll
        for (int mt = 0; mt < 2; mt++) {
#pragma unroll
            for (int nt = 0; nt < 8; nt++) {
                int col = bn + n0 + nt * 8 + cc;
                float bx = bias[col], by = bias[col + 1];
                int row = bm + m0 + mt * 16 + cr;
                float2 v0, v1;
                v0.x = acc[mt][nt][0] + bx;
                v0.y = acc[mt][nt][1] + by;
                v1.x = acc[mt][nt][2] + bx;
                v1.y = acc[mt][nt][3] + by;
                if (mode == 1) {
                    v0.x = fmaxf(v0.x, 0.f); v0.y = fmaxf(v0.y, 0.f);
                    v1.x = fmaxf(v1.x, 0.f); v1.y = fmaxf(v1.y, 0.f);
                }
                *(float2*)(C + (size_t)row * N + col) = v0;
                *(float2*)(C + (size_t)(row + 8) * N + col) = v1;
            }
        }
    } else {
        size_t eN3 = 3 * (size_t)N;
#pragma unroll
        for (int mt = 0; mt < 2; mt++) {
#pragma unroll
            for (int nt = 0; nt < 8; nt++) {
                int col = bn + n0 + nt * 8 + cc;
                float bx = bias[col], by = bias[col + 1];
                int row = bm + m0 + mt * 16 + cr;
                float a0 = acc[mt][nt][0] + bx;
                float a1 = acc[mt][nt][1] + by;
                float a2 = acc[mt][nt][2] + bx;
                float a3 = acc[mt][nt][3] + by;
                if (mode == 2) {
                    a0 = fmaxf(a0, 0.f); a1 = fmaxf(a1, 0.f);
                    a2 = fmaxf(a2, 0.f); a3 = fmaxf(a3, 0.f);
                }
                ext3_store2(E + (size_t)row * eN3, N, col, a0, a1);
                ext3_store2(E + (size_t)(row + 8) * eN3, N, col, a2, a3);
            }
        }
    }
}

// ==================== flash attention =======================================
// Q,K from g_qk (stride 2048, K at +1024), V stride 1024. Out: ext -> E.
__global__ __launch_bounds__(256, 2) void attn_kernel(
    const float* __restrict__ QK, const float* __restrict__ V,
    __nv_bfloat16* __restrict__ E) {
    __shared__ float Qs[32][68];
    __shared__ float Ks[2][32][68];
    __shared__ float Vs[2][32][68];
    __shared__ float Ps[32][33];
    int h = blockIdx.y;
    int s0 = blockIdx.x * 32;
    int tid = threadIdx.x;
    int lrow = tid >> 3;
    int lc0 = (tid & 7) * 8;
    int r = lrow, lane = tid & 7;
    const float* Kb = QK + 1024;

    {
        const float* src = QK + (size_t)(s0 + lrow) * 2048 + h * HD + lc0;
        *(float4*)&Qs[lrow][lc0] = *(const float4*)src;
        *(float4*)&Qs[lrow][lc0 + 4] = *(const float4*)(src + 4);
    }
    __syncthreads();
    float qr[64];
#pragma unroll
    for (int d = 0; d < 64; d += 4)
        *(float4*)&qr[d] = *(float4*)&Qs[r][d];

#define PFT(t, b)                                                        \
    {                                                                    \
        const float* ks = Kb + (size_t)((t) * 32 + lrow) * 2048 + h * HD + lc0; \
        const float* vs = V + (size_t)((t) * 32 + lrow) * 1024 + h * HD + lc0;  \
        uint32_t ka = smem_u32(&Ks[b][lrow][lc0]);                       \
        uint32_t va = smem_u32(&Vs[b][lrow][lc0]);                       \
        cp_async16(ka, ks);                                              \
        cp_async16(ka + 16, ks + 4);                                     \
        cp_async16(va, vs);                                              \
        cp_async16(va + 16, vs + 4);                                     \
        asm volatile("cp.async.commit_group;" ::: "memory");             \
    }

    float m = -INFINITY, l = 0.f;
    float acc[8];
#pragma unroll
    for (int j = 0; j < 8; j++) acc[j] = 0.f;
    const float scale = 0.125f;

    PFT(0, 0)
    for (int t = 0; t < 64; t++) {
        int b = t & 1;
        if (t + 1 < 64) {
            PFT(t + 1, b ^ 1)
            asm volatile("cp.async.wait_group 1;" ::: "memory");
        } else {
            asm volatile("cp.async.wait_group 0;" ::: "memory");
        }
        __syncthreads();

        float sc[4];
#pragma unroll
        for (int c4 = 0; c4 < 4; c4++) {
            int col = lane + c4 * 8;
            float sum = 0.f;
#pragma unroll
            for (int d = 0; d < 64; d += 4) {
                float4 kv = *(float4*)&Ks[b][col][d];
                sum += qr[d] * kv.x + qr[d + 1] * kv.y +
                       qr[d + 2] * kv.z + qr[d + 3] * kv.w;
            }
            sc[c4] = sum * scale;
        }
        float tmax = fmaxf(fmaxf(sc[0], sc[1]), fmaxf(sc[2], sc[3]));
#pragma unroll
        for (int off = 1; off < 8; off <<= 1)
            tmax = fmaxf(tmax, __shfl_xor_sync(0xffffffffu, tmax, off));
        float newm = fmaxf(m, tmax);
        float corr = expf(m - newm);
        float psum = 0.f;
#pragma unroll
        for (int c4 = 0; c4 < 4; c4++) {
            float p = expf(sc[c4] - newm);
            Ps[r][lane + c4 * 8] = p;
            psum += p;
        }
#pragma unroll
        for (int off = 1; off < 8; off <<= 1)
            psum += __shfl_xor_sync(0xffffffffu, psum, off);
        l = l * corr + psum;
        m = newm;
#pragma unroll
        for (int j = 0; j < 8; j++) acc[j] *= corr;
        __syncwarp();
#pragma unroll 4
        for (int c = 0; c < 32; c++) {
            float p = Ps[r][c];
            float4 v0 = *(float4*)&Vs[b][c][lane * 8];
            float4 v1 = *(float4*)&Vs[b][c][lane * 8 + 4];
            acc[0] += p * v0.x; acc[1] += p * v0.y;
            acc[2] += p * v0.z; acc[3] += p * v0.w;
            acc[4] += p * v1.x; acc[5] += p * v1.y;
            acc[6] += p * v1.z; acc[7] += p * v1.w;
        }
        __syncthreads();  // all reads of buf done before next PFT overwrites
    }
#undef PFT

    float inv = 1.f / l;
    int colg = h * HD + lane * 8;
    __nv_bfloat16* row = E + (size_t)(s0 + r) * 3072;
#pragma unroll
    for (int j = 0; j < 8; j += 2)
        ext3_store2(row, D, colg + j, acc[j] * inv, acc[j + 1] * inv);
}

// ==================== layernorm (+ext) / logits =============================
__device__ __forceinline__ float block_sum256(float v, float* sbuf) {
    int tid = threadIdx.x;
#pragma unroll
    for (int off = 16; off > 0; off >>= 1)
        v += __shfl_xor_sync(0xffffffffu, v, off);
    if ((tid & 31) == 0) sbuf[tid >> 5] = v;
    __syncthreads();
    if (tid < 32) {
        float w = (tid < 8) ? sbuf[tid] : 0.f;
#pragma unroll
        for (int off = 4; off > 0; off >>= 1)
            w += __shfl_xor_sync(0xffffffffu, w, off);
        if (tid == 0) sbuf[0] = w;
    }
    __syncthreads();
    float r = sbuf[0];
    __syncthreads();
    return r;
}

__global__ __launch_bounds__(256) void addln_ext(
    const float* __restrict__ x, const float* __restrict__ res,
    const float* __restrict__ g, const float* __restrict__ b,
    float* __restrict__ xo, __nv_bfloat16* __restrict__ e) {
    __shared__ float sbuf[8];
    int s = blockIdx.x;
    int tid = threadIdx.x;
    float v[4];
    float loc = 0.f;
#pragma unroll
    for (int i = 0; i < 4; i++) {
        int d = tid + i * 256;
        v[i] = x[(size_t)s * D + d] + res[(size_t)s * D + d];
        loc += v[i];
    }
    float mean = block_sum256(loc, sbuf) * (1.f / D);
    float lv = 0.f;
#pragma unroll
    for (int i = 0; i < 4; i++) {
        float dd = v[i] - mean;
        lv += dd * dd;
    }
    float var = block_sum256(lv, sbuf) * (1.f / D);
    float rstd = rsqrtf(var + 1e-5f);
    __nv_bfloat16* row = e + (size_t)s * 3072;
#pragma unroll
    for (int i = 0; i < 4; i++) {
        int d = tid + i * 256;
        float o = (v[i] - mean) * rstd * g[d] + b[d];
        xo[(size_t)s * D + d] = o;
        __nv_bfloat16 hi = __float2bfloat16(o);
        row[d] = hi;
        row[1024 + d] = hi;
        row[2048 + d] = __float2bfloat16(o - __bfloat162float(hi));
    }
}

__global__ __launch_bounds__(256) void logits_kernel(
    const float* __restrict__ hfeat, const float* __restrict__ w,
    const float* __restrict__ b, float* __restrict__ out) {
    __shared__ float sbuf[8];
    int s = blockIdx.x;
    int tid = threadIdx.x;
    float loc = 0.f;
#pragma unroll
    for (int i = 0; i < 4; i++) {
        int d = tid + i * 256;
        loc += hfeat[(size_t)s * MH + d] * w[d];
    }
    float total = block_sum256(loc, sbuf);
    if (tid == 0) out[s] = total + b[0];
}

// ==================== launch ================================================
extern "C" void kernel_launch(void* const* d_in, const int* in_sizes, int n_in,
                              void* d_out, int out_size) {
    const float* node_emb = (const float*)d_in[0];
    const int*   tile_ids = (const int*)d_in[1];
    const int*   ny       = (const int*)d_in[2];
    const float* wq  = (const float*)d_in[3];
    const float* wk  = (const float*)d_in[4];
    const float* wv  = (const float*)d_in[5];
    const float* bq  = (const float*)d_in[6];
    const float* bk  = (const float*)d_in[7];
    const float* bv  = (const float*)d_in[8];
    const float* wo  = (const float*)d_in[9];
    const float* bo  = (const float*)d_in[10];
    const float* w1  = (const float*)d_in[11];
    const float* b1  = (const float*)d_in[12];
    const float* w2  = (const float*)d_in[13];
    const float* b2  = (const float*)d_in[14];
    const float* g1  = (const float*)d_in[15];
    const float* be1 = (const float*)d_in[16];
    const float* g2  = (const float*)d_in[17];
    const float* be2 = (const float*)d_in[18];
    const float* ws0 = (const float*)d_in[19];
    const float* bs0 = (const float*)d_in[20];
    const float* ws1 = (const float*)d_in[21];
    const float* bs1 = (const float*)d_in[22];
    const float* ws2 = (const float*)d_in[23];
    const float* bs2 = (const float*)d_in[24];
    float* out = (float*)d_out;

    float *x, *qk, *v, *tmp, *bias2;
    __nv_bfloat16 *wext, *aA, *aB;
    cudaGetSymbolAddress((void**)&x,     g_x);
    cudaGetSymbolAddress((void**)&qk,    g_qk);
    cudaGetSymbolAddress((void**)&v,     g_v);
    cudaGetSymbolAddress((void**)&tmp,   g_tmp);
    cudaGetSymbolAddress((void**)&bias2, g_bias2);
    cudaGetSymbolAddress((void**)&wext,  g_wext);
    cudaGetSymbolAddress((void**)&aA,    g_aextA);
    cudaGetSymbolAddress((void**)&aB,    g_aextB);

    dim3 cw8(32, 8);
    dim3 gDD(8, 16);      // N=1024 gemm grid
    dim3 gDF(16, 16);     // N=2048 gemm grid
    dim3 gAttn(64, 16);

    // launch #0
    gather_ext<<<S, 256>>>(node_emb, tile_ids, x, aB);

    for (int l = 0; l < L; l++) {
        long long woff = (long long)l * PER_LAYER;
        const size_t oD = (size_t)l * D;
        const size_t oF = (size_t)l * FF;

        rope_ext<<<S, 256>>>(x, tile_ids, ny, aA);
        convert_w<<<dim3(32, 32), cw8>>>(wq + (size_t)l * D * D, wext + woff + WQo, D, D);
        convert_w<<<dim3(32, 32), cw8>>>(wk + (size_t)l * D * D, wext + woff + WKo, D, D);
        concat_bias<<<8, 256>>>(bq + oD, bk + oD, bias2);
        // launch #5 on l==0 -> profiled by ncu
        gemm_mma<<<gDF, 256>>>(aA, wext + woff + WQo, bias2, qk, aA, 2048, 3072, 0);
        convert_w<<<dim3(32, 32), cw8>>>(wv + (size_t)l * D * D, wext + woff + WVo, D, D);
        gemm_mma<<<gDD, 256>>>(aB, wext + woff + WVo, bv + oD, v, aA, 1024, 3072, 0);
        attn_kernel<<<gAttn, 256>>>(qk, v, aA);
        convert_w<<<dim3(32, 32), cw8>>>(wo + (size_t)l * D * D, wext + woff + WOo, D, D);
        gemm_mma<<<gDD, 256>>>(aA, wext + woff + WOo, bo + oD, tmp, aA, 1024, 3072, 0);
        addln_ext<<<S, 256>>>(x, tmp, g1 + oD, be1 + oD, x, aB);
        convert_w<<<dim3(64, 32), cw8>>>(w1 + (size_t)l * D * FF, wext + woff + W1o, D, FF);
        gemm_mma<<<gDF, 256>>>(aB, wext + woff + W1o, b1 + oF, tmp, aA, 2048, 3072, 2);
        convert_w<<<dim3(32, 64), cw8>>>(w2 + (size_t)l * FF * D, wext + woff + W2o, FF, D);
        gemm_mma<<<gDD, 256>>>(aA, wext + woff + W2o, b2 + oD, tmp, aA, 1024, 6144, 0);
        addln_ext<<<S, 256>>>(x, tmp, g2 + oD, be2 + oD, x, aB);
    }

    convert_w<<<dim3(32, 32), cw8>>>(ws0, wext + WS0o, D, MH);
    gemm_mma<<<gDD, 256>>>(aB, wext + WS0o, bs0, tmp, aA, 1024, 3072, 2);
    convert_w<<<dim3(32, 32), cw8>>>(ws1, wext + WS1o, MH, MH);
    gemm_mma<<<gDD, 256>>>(aA, wext + WS1o, bs1, tmp, aA, 1024, 3072, 1);
    logits_kernel<<<S, 256>>>(tmp, ws2, bs2, out);
}

// round 7
// speedup vs baseline: 1.3536x; 1.0235x over previous
#include <cuda_runtime.h>
#include <cuda_bf16.h>
#include <math.h>
#include <stdint.h>

#define S  2048
#define D  1024
#define H  16
#define HD 64
#define L  2
#define MH 1024
#define FF 2048

// ---------------- scratch (device globals) ----------------------------------
__device__ float g_x[S * D];          // residual stream (fp32)
__device__ float g_qk[S * 2048];      // fused q|k output
__device__ float g_v[S * D];
__device__ float g_tmp[S * D];        // attn_out / ff2 out / head h2
// bf16x3 weights
#define PER_LAYER 25165824ll
#define WQo 0ll
#define WKo 3145728ll
#define WVo 6291456ll
#define WOo 9437184ll
#define W1o 12582912ll
#define W2o 18874368ll
#define WS0o (2ll * PER_LAYER)
#define WS1o (WS0o + 3145728ll)
__device__ __nv_bfloat16 g_wext[56623104ll];
__device__ __nv_bfloat16 g_aextA[(size_t)S * 6144];
__device__ __nv_bfloat16 g_aextB[(size_t)S * 6144];

// ==================== PTX helpers ===========================================
__device__ __forceinline__ uint32_t smem_u32(const void* p) {
    return (uint32_t)__cvta_generic_to_shared(p);
}
__device__ __forceinline__ void cp_async16(uint32_t s, const void* g) {
    asm volatile("cp.async.cg.shared.global [%0], [%1], 16;" :: "r"(s), "l"(g));
}
__device__ __forceinline__ void ldsm4(uint32_t* r, uint32_t addr) {
    asm volatile("ldmatrix.sync.aligned.m8n8.x4.shared.b16 {%0,%1,%2,%3}, [%4];"
                 : "=r"(r[0]), "=r"(r[1]), "=r"(r[2]), "=r"(r[3]) : "r"(addr));
}
__device__ __forceinline__ void mma16816(float* c, const uint32_t* a,
                                         const uint32_t* b) {
    asm volatile(
        "mma.sync.aligned.m16n8k16.row.col.f32.bf16.bf16.f32 "
        "{%0,%1,%2,%3}, {%4,%5,%6,%7}, {%8,%9}, {%0,%1,%2,%3};"
        : "+f"(c[0]), "+f"(c[1]), "+f"(c[2]), "+f"(c[3])
        : "r"(a[0]), "r"(a[1]), "r"(a[2]), "r"(a[3]), "r"(b[0]), "r"(b[1]));
}
__device__ __forceinline__ void ext3_store2(__nv_bfloat16* row, int N, int col,
                                            float v0, float v1) {
    __nv_bfloat162 h2, l2;
    h2.x = __float2bfloat16(v0);
    h2.y = __float2bfloat16(v1);
    l2.x = __float2bfloat16(v0 - __bfloat162float(h2.x));
    l2.y = __float2bfloat16(v1 - __bfloat162float(h2.y));
    *(__nv_bfloat162*)(row + col) = h2;
    *(__nv_bfloat162*)(row + N + col) = h2;
    *(__nv_bfloat162*)(row + 2 * N + col) = l2;
}

// ==================== weight conversion =====================================
// W [K,N] fp32 -> Wext [N, 3K] bf16 : [hi | lo | hi]
__global__ void convert_w(const float* __restrict__ W,
                          __nv_bfloat16* __restrict__ dst, int K, int N) {
    __shared__ float t[32][33];
    int k0 = blockIdx.y * 32, n0 = blockIdx.x * 32;
    int tx = threadIdx.x, ty = threadIdx.y;
    for (int i = ty; i < 32; i += 8)
        t[i][tx] = W[(size_t)(k0 + i) * N + n0 + tx];
    __syncthreads();
    size_t K3 = 3 * (size_t)K;
    for (int i = ty; i < 32; i += 8) {
        int n = n0 + i, k = k0 + tx;
        float v = t[tx][i];
        __nv_bfloat16 hi = __float2bfloat16(v);
        __nv_bfloat16 lo = __float2bfloat16(v - __bfloat162float(hi));
        __nv_bfloat16* row = dst + (size_t)n * K3;
        row[k] = hi;
        row[K + k] = lo;
        row[2 * K + k] = hi;
    }
}

// ==================== fused gather + rope (layer 0) =========================
__global__ void gather_rope_ext(const float* __restrict__ emb,
                                const int* __restrict__ ids,
                                const int* __restrict__ nyp,
                                float* __restrict__ x,
                                __nv_bfloat16* __restrict__ eB,
                                __nv_bfloat16* __restrict__ eA) {
    int s = blockIdx.x;
    int j = threadIdx.x;  // 0..255
    int id = ids[s];
    int Ny = nyp[0];
    const float* src = emb + (size_t)id * D;
    float x1 = src[j], x2 = src[j + 256];
    float y1 = src[j + 512], y2 = src[j + 768];
    // residual stream
    float* xd = x + (size_t)s * D;
    xd[j] = x1; xd[j + 256] = x2; xd[j + 512] = y1; xd[j + 768] = y2;
#define E1(row, d, v)                                                   \
    {                                                                   \
        __nv_bfloat16 hi = __float2bfloat16(v);                         \
        (row)[d] = hi;                                                  \
        (row)[1024 + (d)] = hi;                                         \
        (row)[2048 + (d)] = __float2bfloat16((v) - __bfloat162float(hi)); \
    }
    // plain ext (for V gemm)
    __nv_bfloat16* rb = eB + (size_t)s * 3072;
    E1(rb, j, x1) E1(rb, j + 256, x2) E1(rb, j + 512, y1) E1(rb, j + 768, y2)
    // roped ext (for QK gemm)
    float rowp = (float)(id / Ny);
    float colp = (float)(id % Ny);
    float theta = powf(10000.f, -((float)j) * (1.f / 256.f));
    float s1, c1, s2, c2;
    sincosf(rowp * theta, &s1, &c1);
    sincosf(colp * theta, &s2, &c2);
    float o0 = x1 * c1 - x2 * s1;
    float o1 = x1 * s1 + x2 * c1;
    float o2 = y1 * c2 - y2 * s2;
    float o3 = y1 * s2 + y2 * c2;
    __nv_bfloat16* ra = eA + (size_t)s * 3072;
    E1(ra, j, o0) E1(ra, j + 256, o1) E1(ra, j + 512, o2) E1(ra, j + 768, o3)
}

// ==================== 2D RoPE (+ext) for layer >= 1 =========================
__global__ void rope_ext(const float* __restrict__ x,
                         const int* __restrict__ ids,
                         const int* __restrict__ nyp,
                         __nv_bfloat16* __restrict__ e) {
    int s = blockIdx.x;
    int j = threadIdx.x;
    int id = ids[s];
    int Ny = nyp[0];
    float rowp = (float)(id / Ny);
    float colp = (float)(id % Ny);
    float theta = powf(10000.f, -((float)j) * (1.f / 256.f));
    float s1, c1, s2, c2;
    sincosf(rowp * theta, &s1, &c1);
    sincosf(colp * theta, &s2, &c2);
    const float* xs = x + (size_t)s * D;
    __nv_bfloat16* row = e + (size_t)s * 3072;
    float x1 = xs[j], x2 = xs[j + 256];
    float y1 = xs[j + 512], y2 = xs[j + 768];
    float o0 = x1 * c1 - x2 * s1;
    float o1 = x1 * s1 + x2 * c1;
    float o2 = y1 * c2 - y2 * s2;
    float o3 = y1 * s2 + y2 * c2;
    E1(row, j, o0) E1(row, j + 256, o1) E1(row, j + 512, o2) E1(row, j + 768, o3)
}
#undef E1

// ==================== mma.sync GEMM, 3-stage pipeline =======================
// C[M,N] = Aext[M,K3] x Wext[N,K3]^T + bias.
// bias: col<1024 -> biasA[col], else biasB[col-1024].
// mode 0: fp32 C; 1: fp32+relu; 2: ext E+relu; 3: ext E.
#define STG 16384
__global__ __launch_bounds__(256, 2) void gemm_mma(
    const __nv_bfloat16* __restrict__ A, const __nv_bfloat16* __restrict__ B,
    const float* __restrict__ biasA, const float* __restrict__ biasB,
    float* __restrict__ C, __nv_bfloat16* __restrict__ E,
    int N, int K3, int mode) {
    __shared__ __align__(16) char smem[49152];
    int tid = threadIdx.x;
    int bm = blockIdx.y * 128, bn = blockIdx.x * 128;
    int wid = tid >> 5, lane = tid & 31;
    int m0 = (wid & 3) * 32, n0 = (wid >> 2) * 64;
    uint32_t sb = smem_u32(smem);

    int lrow = tid >> 1, lsub = (tid & 1) * 2;
    const char* gA = (const char*)(A + (size_t)(bm + lrow) * K3);
    const char* gB = (const char*)(B + (size_t)(bn + lrow) * K3);
    uint32_t rowOff = (uint32_t)lrow * 64u;
    uint32_t swA0 = (uint32_t)((lsub ^ (lrow & 3)) * 16);
    uint32_t swA1 = (uint32_t)(((lsub + 1) ^ (lrow & 3)) * 16);

#define PF(kc, st)                                                     \
    {                                                                  \
        const char* pa = gA + (size_t)(kc) * 64 + lsub * 16;           \
        const char* pb = gB + (size_t)(kc) * 64 + lsub * 16;           \
        uint32_t ba = sb + (uint32_t)(st) * STG + rowOff;              \
        uint32_t bb = ba + 8192u;                                      \
        cp_async16(ba + swA0, pa);                                     \
        cp_async16(ba + swA1, pa + 16);                                \
        cp_async16(bb + swA0, pb);                                     \
        cp_async16(bb + swA1, pb + 16);                                \
        asm volatile("cp.async.commit_group;" ::: "memory");           \
    }

    int a_r = (lane & 7) + ((lane >> 3) & 1) * 8;
    int a_s = lane >> 4;
    int b_r = (lane & 7) + ((lane >> 4) & 1) * 8;
    int b_s = (lane >> 3) & 1;
    uint32_t aRow[2]; int aSw[2];
#pragma unroll
    for (int mt = 0; mt < 2; mt++) {
        int row = m0 + mt * 16 + a_r;
        aRow[mt] = (uint32_t)row * 64u;
        aSw[mt] = row & 3;
    }
    uint32_t bRow[4]; int bSw[4];
#pragma unroll
    for (int p = 0; p < 4; p++) {
        int row = n0 + p * 16 + b_r;
        bRow[p] = (uint32_t)row * 64u;
        bSw[p] = row & 3;
    }

    float acc[2][8][4];
#pragma unroll
    for (int mt = 0; mt < 2; mt++)
#pragma unroll
        for (int nt = 0; nt < 8; nt++)
#pragma unroll
            for (int e = 0; e < 4; e++) acc[mt][nt][e] = 0.f;

    int NC = K3 >> 5;
    PF(0, 0)
    PF(1, 1)
    int st = 0;
    for (int c = 0; c < NC; c++) {
        if (c + 1 < NC)
            asm volatile("cp.async.wait_group 1;" ::: "memory");
        else
            asm volatile("cp.async.wait_group 0;" ::: "memory");
        __syncthreads();
        if (c + 2 < NC) {
            int s2 = st + 2;
            if (s2 >= 3) s2 -= 3;
            PF(c + 2, s2)
        }
        uint32_t base = sb + (uint32_t)st * STG;
#pragma unroll
        for (int h = 0; h < 2; h++) {
            uint32_t afr[2][4];
#pragma unroll
            for (int mt = 0; mt < 2; mt++)
                ldsm4(afr[mt], base + aRow[mt] +
                                   (uint32_t)(((a_s + 2 * h) ^ aSw[mt]) * 16));
            uint32_t bfr[8][2];
#pragma unroll
            for (int p = 0; p < 4; p++) {
                uint32_t r[4];
                ldsm4(r, base + 8192u + bRow[p] +
                             (uint32_t)(((b_s + 2 * h) ^ bSw[p]) * 16));
                bfr[2 * p][0] = r[0];
                bfr[2 * p][1] = r[1];
                bfr[2 * p + 1][0] = r[2];
                bfr[2 * p + 1][1] = r[3];
            }
#pragma unroll
            for (int mt = 0; mt < 2; mt++)
#pragma unroll
                for (int nt = 0; nt < 8; nt++)
                    mma16816(acc[mt][nt], afr[mt], bfr[nt]);
        }
        st = (st == 2) ? 0 : st + 1;
    }
#undef PF

    int cr = lane >> 2;
    int cc = (lane & 3) * 2;
#pragma unroll
    for (int mt = 0; mt < 2; mt++) {
#pragma unroll
        for (int nt = 0; nt < 8; nt++) {
            int col = bn + n0 + nt * 8 + cc;
            float bx = (col < 1024) ? biasA[col] : biasB[col - 1024];
            float by = (col + 1 < 1024) ? biasA[col + 1] : biasB[col - 1023];
            int row = bm + m0 + mt * 16 + cr;
            float a0 = acc[mt][nt][0] + bx;
            float a1 = acc[mt][nt][1] + by;
            float a2 = acc[mt][nt][2] + bx;
            float a3 = acc[mt][nt][3] + by;
            if (mode == 1 || mode == 2) {
                a0 = fmaxf(a0, 0.f); a1 = fmaxf(a1, 0.f);
                a2 = fmaxf(a2, 0.f); a3 = fmaxf(a3, 0.f);
            }
            if (mode <= 1) {
                *(float2*)(C + (size_t)row * N + col) = make_float2(a0, a1);
                *(float2*)(C + (size_t)(row + 8) * N + col) = make_float2(a2, a3);
            } else {
                size_t eN3 = 3 * (size_t)N;
                ext3_store2(E + (size_t)row * eN3, N, col, a0, a1);
                ext3_store2(E + (size_t)(row + 8) * eN3, N, col, a2, a3);
            }
        }
    }
}

// ==================== flash attention =======================================
__global__ __launch_bounds__(256, 2) void attn_kernel(
    const float* __restrict__ QK, const float* __restrict__ V,
    __nv_bfloat16* __restrict__ E) {
    __shared__ float Qs[32][68];
    __shared__ float Ks[2][32][68];
    __shared__ float Vs[2][32][68];
    __shared__ float Ps[32][33];
    int h = blockIdx.y;
    int s0 = blockIdx.x * 32;
    int tid = threadIdx.x;
    int lrow = tid >> 3;
    int lc0 = (tid & 7) * 8;
    int r = lrow, lane = tid & 7;
    const float* Kb = QK + 1024;

    {
        const float* src = QK + (size_t)(s0 + lrow) * 2048 + h * HD + lc0;
        *(float4*)&Qs[lrow][lc0] = *(const float4*)src;
        *(float4*)&Qs[lrow][lc0 + 4] = *(const float4*)(src + 4);
    }
    __syncthreads();
    float qr[64];
#pragma unroll
    for (int d = 0; d < 64; d += 4)
        *(float4*)&qr[d] = *(float4*)&Qs[r][d];

#define PFT(t, b)                                                        \
    {                                                                    \
        const float* ks = Kb + (size_t)((t) * 32 + lrow) * 2048 + h * HD + lc0; \
        const float* vs = V + (size_t)((t) * 32 + lrow) * 1024 + h * HD + lc0;  \
        uint32_t ka = smem_u32(&Ks[b][lrow][lc0]);                       \
        uint32_t va = smem_u32(&Vs[b][lrow][lc0]);                       \
        cp_async16(ka, ks);                                              \
        cp_async16(ka + 16, ks + 4);                                     \
        cp_async16(va, vs);                                              \
        cp_async16(va + 16, vs + 4);                                     \
        asm volatile("cp.async.commit_group;" ::: "memory");             \
    }

    float m = -INFINITY, l = 0.f;
    float acc[8];
#pragma unroll
    for (int j = 0; j < 8; j++) acc[j] = 0.f;
    const float scale = 0.125f;

    PFT(0, 0)
    for (int t = 0; t < 64; t++) {
        int b = t & 1;
        if (t + 1 < 64) {
            PFT(t + 1, b ^ 1)
            asm volatile("cp.async.wait_group 1;" ::: "memory");
        } else {
            asm volatile("cp.async.wait_group 0;" ::: "memory");
        }
        __syncthreads();

        float sc[4];
#pragma unroll
        for (int c4 = 0; c4 < 4; c4++) {
            int col = lane + c4 * 8;
            float sum = 0.f;
#pragma unroll
            for (int d = 0; d < 64; d += 4) {
                float4 kv = *(float4*)&Ks[b][col][d];
                sum += qr[d] * kv.x + qr[d + 1] * kv.y +
                       qr[d + 2] * kv.z + qr[d + 3] * kv.w;
            }
            sc[c4] = sum * scale;
        }
        float tmax = fmaxf(fmaxf(sc[0], sc[1]), fmaxf(sc[2], sc[3]));
#pragma unroll
        for (int off = 1; off < 8; off <<= 1)
            tmax = fmaxf(tmax, __shfl_xor_sync(0xffffffffu, tmax, off));
        float newm = fmaxf(m, tmax);
        float corr = (m == -INFINITY) ? 0.f : __expf(m - newm);
        float psum = 0.f;
#pragma unroll
        for (int c4 = 0; c4 < 4; c4++) {
            float p = __expf(sc[c4] - newm);
            Ps[r][lane + c4 * 8] = p;
            psum += p;
        }
#pragma unroll
        for (int off = 1; off < 8; off <<= 1)
            psum += __shfl_xor_sync(0xffffffffu, psum, off);
        l = l * corr + psum;
        m = newm;
#pragma unroll
        for (int j = 0; j < 8; j++) acc[j] *= corr;
        __syncwarp();
#pragma unroll 4
        for (int c = 0; c < 32; c++) {
            float p = Ps[r][c];
            float4 v0 = *(float4*)&Vs[b][c][lane * 8];
            float4 v1 = *(float4*)&Vs[b][c][lane * 8 + 4];
            acc[0] += p * v0.x; acc[1] += p * v0.y;
            acc[2] += p * v0.z; acc[3] += p * v0.w;
            acc[4] += p * v1.x; acc[5] += p * v1.y;
            acc[6] += p * v1.z; acc[7] += p * v1.w;
        }
        __syncthreads();
    }
#undef PFT

    float inv = 1.f / l;
    int colg = h * HD + lane * 8;
    __nv_bfloat16* row = E + (size_t)(s0 + r) * 3072;
#pragma unroll
    for (int j = 0; j < 8; j += 2)
        ext3_store2(row, D, colg + j, acc[j] * inv, acc[j + 1] * inv);
}

// ==================== layernorm (+ext) / logits =============================
__device__ __forceinline__ float block_sum256(float v, float* sbuf) {
    int tid = threadIdx.x;
#pragma unroll
    for (int off = 16; off > 0; off >>= 1)
        v += __shfl_xor_sync(0xffffffffu, v, off);
    if ((tid & 31) == 0) sbuf[tid >> 5] = v;
    __syncthreads();
    if (tid < 32) {
        float w = (tid < 8) ? sbuf[tid] : 0.f;
#pragma unroll
        for (int off = 4; off > 0; off >>= 1)
            w += __shfl_xor_sync(0xffffffffu, w, off);
        if (tid == 0) sbuf[0] = w;
    }
    __syncthreads();
    float r = sbuf[0];
    __syncthreads();
    return r;
}

__global__ __launch_bounds__(256) void addln_ext(
    const float* __restrict__ x, const float* __restrict__ res,
    const float* __restrict__ g, const float* __restrict__ b,
    float* __restrict__ xo, __nv_bfloat16* __restrict__ e) {
    __shared__ float sbuf[8];
    int s = blockIdx.x;
    int tid = threadIdx.x;
    float v[4];
    float loc = 0.f;
#pragma unroll
    for (int i = 0; i < 4; i++) {
        int d = tid + i * 256;
        v[i] = x[(size_t)s * D + d] + res[(size_t)s * D + d];
        loc += v[i];
    }
    float mean = block_sum256(loc, sbuf) * (1.f / D);
    float lv = 0.f;
#pragma unroll
    for (int i = 0; i < 4; i++) {
        float dd = v[i] - mean;
        lv += dd * dd;
    }
    float var = block_sum256(lv, sbuf) * (1.f / D);
    float rstd = rsqrtf(var + 1e-5f);
    __nv_bfloat16* row = e + (size_t)s * 3072;
#pragma unroll
    for (int i = 0; i < 4; i++) {
        int d = tid + i * 256;
        float o = (v[i] - mean) * rstd * g[d] + b[d];
        xo[(size_t)s * D + d] = o;
        __nv_bfloat16 hi = __float2bfloat16(o);
        row[d] = hi;
        row[1024 + d] = hi;
        row[2048 + d] = __float2bfloat16(o - __bfloat162float(hi));
    }
}

__global__ __launch_bounds__(256) void logits_kernel(
    const float* __restrict__ hfeat, const float* __restrict__ w,
    const float* __restrict__ b, float* __restrict__ out) {
    __shared__ float sbuf[8];
    int s = blockIdx.x;
    int tid = threadIdx.x;
    float loc = 0.f;
#pragma unroll
    for (int i = 0; i < 4; i++) {
        int d = tid + i * 256;
        loc += hfeat[(size_t)s * MH + d] * w[d];
    }
    float total = block_sum256(loc, sbuf);
    if (tid == 0) out[s] = total + b[0];
}

// ==================== launch ================================================
extern "C" void kernel_launch(void* const* d_in, const int* in_sizes, int n_in,
                              void* d_out, int out_size) {
    const float* node_emb = (const float*)d_in[0];
    const int*   tile_ids = (const int*)d_in[1];
    const int*   ny       = (const int*)d_in[2];
    const float* wq  = (const float*)d_in[3];
    const float* wk  = (const float*)d_in[4];
    const float* wv  = (const float*)d_in[5];
    const float* bq  = (const float*)d_in[6];
    const float* bk  = (const float*)d_in[7];
    const float* bv  = (const float*)d_in[8];
    const float* wo  = (const float*)d_in[9];
    const float* bo  = (const float*)d_in[10];
    const float* w1  = (const float*)d_in[11];
    const float* b1  = (const float*)d_in[12];
    const float* w2  = (const float*)d_in[13];
    const float* b2  = (const float*)d_in[14];
    const float* g1  = (const float*)d_in[15];
    const float* be1 = (const float*)d_in[16];
    const float* g2  = (const float*)d_in[17];
    const float* be2 = (const float*)d_in[18];
    const float* ws0 = (const float*)d_in[19];
    const float* bs0 = (const float*)d_in[20];
    const float* ws1 = (const float*)d_in[21];
    const float* bs1 = (const float*)d_in[22];
    const float* ws2 = (const float*)d_in[23];
    const float* bs2 = (const float*)d_in[24];
    float* out = (float*)d_out;

    float *x, *qk, *v, *tmp;
    __nv_bfloat16 *wext, *aA, *aB;
    cudaGetSymbolAddress((void**)&x,    g_x);
    cudaGetSymbolAddress((void**)&qk,   g_qk);
    cudaGetSymbolAddress((void**)&v,    g_v);
    cudaGetSymbolAddress((void**)&tmp,  g_tmp);
    cudaGetSymbolAddress((void**)&wext, g_wext);
    cudaGetSymbolAddress((void**)&aA,   g_aextA);
    cudaGetSymbolAddress((void**)&aB,   g_aextB);

    dim3 cw8(32, 8);
    dim3 gDD(8, 16);
    dim3 gDF(16, 16);
    dim3 gAttn(64, 16);

    for (int l = 0; l < L; l++) {
        long long woff = (long long)l * PER_LAYER;
        const size_t oD = (size_t)l * D;
        const size_t oF = (size_t)l * FF;

        // launches 0,1 (l=0): wq/wk converts
        convert_w<<<dim3(32, 32), cw8>>>(wq + (size_t)l * D * D, wext + woff + WQo, D, D);
        convert_w<<<dim3(32, 32), cw8>>>(wk + (size_t)l * D * D, wext + woff + WKo, D, D);
        // launch 2 (l=0): fused gather+rope; later layers: rope only
        if (l == 0)
            gather_rope_ext<<<S, 256>>>(node_emb, tile_ids, ny, x, aB, aA);
        else
            rope_ext<<<S, 256>>>(x, tile_ids, ny, aA);
        // launch 3 (l=0): QK gemm  <-- ncu-profiled
        gemm_mma<<<gDF, 256>>>(aA, wext + woff + WQo, bq + oD, bk + oD,
                               qk, aA, 2048, 3072, 0);
        convert_w<<<dim3(32, 32), cw8>>>(wv + (size_t)l * D * D, wext + woff + WVo, D, D);
        gemm_mma<<<gDD, 256>>>(aB, wext + woff + WVo, bv + oD, bv + oD,
                               v, aA, 1024, 3072, 0);
        attn_kernel<<<gAttn, 256>>>(qk, v, aA);
        convert_w<<<dim3(32, 32), cw8>>>(wo + (size_t)l * D * D, wext + woff + WOo, D, D);
        gemm_mma<<<gDD, 256>>>(aA, wext + woff + WOo, bo + oD, bo + oD,
                               tmp, aA, 1024, 3072, 0);
        addln_ext<<<S, 256>>>(x, tmp, g1 + oD, be1 + oD, x, aB);
        convert_w<<<dim3(64, 32), cw8>>>(w1 + (size_t)l * D * FF, wext + woff + W1o, D, FF);
        gemm_mma<<<gDF, 256>>>(aB, wext + woff + W1o, b1 + oF, b1 + oF + 1024,
                               tmp, aA, 2048, 3072, 2);
        convert_w<<<dim3(32, 64), cw8>>>(w2 + (size_t)l * FF * D, wext + woff + W2o, FF, D);
        gemm_mma<<<gDD, 256>>>(aA, wext + woff + W2o, b2 + oD, b2 + oD,
                               tmp, aA, 1024, 6144, 0);
        addln_ext<<<S, 256>>>(x, tmp, g2 + oD, be2 + oD, x, aB);
    }

    convert_w<<<dim3(32, 32), cw8>>>(ws0, wext + WS0o, D, MH);
    gemm_mma<<<gDD, 256>>>(aB, wext + WS0o, bs0, bs0, tmp, aA, 1024, 3072, 2);
    convert_w<<<dim3(32, 32), cw8>>>(ws1, wext + WS1o, MH, MH);
    gemm_mma<<<gDD, 256>>>(aA, wext + WS1o, bs1, bs1, tmp, aA, 1024, 3072, 1);
    logits_kernel<<<S, 256>>>(tmp, ws2, bs2, out);
}